// round 4
// baseline (speedup 1.0000x reference)
#include <cuda_runtime.h>

#define NNODES 50000
#define NEDGES 500000
#define NGRAPHS 500
#define NPG 100
#define FIN 16
#define SCAN_NBLK ((NNODES + 1 + 1023) / 1024)   // 49
#define EMAX 2048                                 // per-graph edge cap for SMEM staging

// ---------------- scratch (device globals; no allocation allowed) ----------------
__device__ float d_h0[NNODES * FIN];
__device__ float d_hA[NNODES * 256];
__device__ float d_hB[NNODES * 256];
__device__ float d_asrc[NNODES * 4];
__device__ float d_adst[NNODES * 4];
__device__ int   d_off[NNODES + 1];
__device__ int   d_cursor[NNODES];
__device__ int   d_srcs[NEDGES];
__device__ int   d_bsum[64];
__device__ float d_pool[NGRAPHS * 68];
__device__ int   d_is64;

// ---------------- small helpers ----------------
__device__ __forceinline__ float lrelu(float x) { return x > 0.f ? x : 0.2f * x; }
__device__ __forceinline__ float elu1(float x) { return x > 0.f ? x : __expf(x) - 1.f; }
__device__ __forceinline__ float seluf(float x) {
    const float a = 1.6732632423543772f, sc = 1.0507009873554805f;
    return x > 0.f ? sc * x : sc * a * expm1f(x);
}

// packed fp32x2 FMA (Blackwell; ptxas never emits this from C++)
__device__ __forceinline__ void ffma2(unsigned long long& d, unsigned long long a,
                                      unsigned long long b) {
    asm("fma.rn.f32x2 %0, %1, %2, %0;" : "+l"(d) : "l"(a), "l"(b));
}
__device__ __forceinline__ float2 unpack2(unsigned long long v) {
    float2 f;
    asm("mov.b64 {%0, %1}, %2;" : "=f"(f.x), "=f"(f.y) : "l"(v));
    return f;
}

__device__ __forceinline__ int load_edge(const void* ei, long long pos) {
    if (d_is64) return (int)((const long long*)ei)[pos];
    return ((const int*)ei)[pos];
}

// ---------------- init: dtype detect + zero counters ----------------
__global__ void init_kernel(const int* ew) {
    int i = blockIdx.x * blockDim.x + threadIdx.x;
    if (i == 0) {
        int ok = 1;
        for (int j = 1; j < 256; j += 2)
            if (ew[j] != 0) ok = 0;
        d_is64 = ok;
    }
    if (i <= NNODES) d_off[i] = 0;
    if (i < NNODES) d_cursor[i] = 0;
}

__global__ void count_kernel(const void* ei) {
    int e = blockIdx.x * blockDim.x + threadIdx.x;
    if (e < NEDGES) {
        int d = load_edge(ei, (long long)NEDGES + e);
        atomicAdd(&d_off[d + 1], 1);
    }
}

// multi-block inclusive scan
__global__ void scan_blocks() {
    __shared__ int s[1024];
    int tid = threadIdx.x;
    int idx = blockIdx.x * 1024 + tid;
    int v = (idx <= NNODES) ? d_off[idx] : 0;
    s[tid] = v;
    __syncthreads();
    for (int off = 1; off < 1024; off <<= 1) {
        int t = (tid >= off) ? s[tid - off] : 0;
        __syncthreads();
        s[tid] += t;
        __syncthreads();
    }
    if (idx <= NNODES) d_off[idx] = s[tid];
    if (tid == 1023) d_bsum[blockIdx.x] = s[1023];
}

__global__ void scan_sums() {
    __shared__ int s[64];
    int tid = threadIdx.x;
    s[tid] = (tid < SCAN_NBLK) ? d_bsum[tid] : 0;
    __syncthreads();
    for (int off = 1; off < 64; off <<= 1) {
        int t = (tid >= off) ? s[tid - off] : 0;
        __syncthreads();
        s[tid] += t;
        __syncthreads();
    }
    d_bsum[tid] = s[tid];
}

__global__ void scan_add() {
    int b = blockIdx.x + 1;
    int idx = b * 1024 + threadIdx.x;
    if (idx <= NNODES) d_off[idx] += d_bsum[b - 1];
}

__global__ void scatter_kernel(const void* ei) {
    int e = blockIdx.x * blockDim.x + threadIdx.x;
    if (e < NEDGES) {
        int sN = load_edge(ei, e);
        int d = load_edge(ei, (long long)NEDGES + e);
        int p = atomicAdd(&d_cursor[d], 1);
        d_srcs[d_off[d] + p] = sN;
    }
}

// ---------------- GraphNorm: one block per graph ----------------
__global__ void graphnorm_kernel(const float* __restrict__ x, const float* __restrict__ w,
                                 const float* __restrict__ b, const float* __restrict__ ms) {
    int g = blockIdx.x;
    __shared__ float red[8][16];
    __shared__ float mv[16], vv[16];
    int t = threadIdx.x;           // 128 threads
    int f = t & 15, i0 = t >> 4;
    const float* xg = x + (size_t)g * NPG * FIN;
    float s = 0.f;
    for (int i = i0; i < NPG; i += 8) s += xg[i * FIN + f];
    red[i0][f] = s;
    __syncthreads();
    if (t < 16) {
        float m = 0.f;
        for (int j = 0; j < 8; j++) m += red[j][t];
        mv[t] = m * (1.f / NPG);
    }
    __syncthreads();
    float mm = mv[f] * ms[f];
    float sv = 0.f;
    for (int i = i0; i < NPG; i += 8) {
        float o = xg[i * FIN + f] - mm;
        sv += o * o;
    }
    __syncthreads();
    red[i0][f] = sv;
    __syncthreads();
    if (t < 16) {
        float v = 0.f;
        for (int j = 0; j < 8; j++) v += red[j][t];
        vv[t] = v * (1.f / NPG);
    }
    __syncthreads();
    float inv = rsqrtf(vv[f] + 1e-5f) * w[f];
    float bb = b[f];
    for (int i = i0; i < NPG; i += 8) {
        float o = xg[i * FIN + f] - mm;
        d_h0[(size_t)(g * NPG + i) * FIN + f] = o * inv + bb;
    }
}

// ---------------- SGEMM: 128x64 tile, 8x8/thread, FFMA2, double-buffered ----------------
// B stored duplicated in SMEM (float2{b,b}) so FFMA2 operands need no packing movs.
// Fused epilogue: d_asrc/d_adst = rowwise dot of C-tile with per-head att vectors.
#define GBM 128
#define GBN 64
#define GBK 16
__global__ void __launch_bounds__(128, 3)
sgemm_att(const float* __restrict__ A, const float* __restrict__ B,
          float* __restrict__ C, int M, int K, int Nn,
          const float* __restrict__ atts, const float* __restrict__ attd, int H) {
    __shared__ float As[2][GBK][GBM];    // 16 KB
    __shared__ float2 Bs[2][GBK][GBN];   // 16 KB (duplicated)

    const int tid = threadIdx.x;         // 128
    const int tx = tid & 7;              // 8 col groups (8 cols each)
    const int ty = tid >> 3;             // 16 row groups (8 rows each)
    const int row0 = blockIdx.x * GBM;
    const int col0 = blockIdx.y * GBN;
    const int hh = blockIdx.y;

    const int a_row = row0 + tid;
    const bool a_ok = a_row < M;
    const float* a_ptr = A + (size_t)(a_ok ? a_row : 0) * K;
    // B staging: thread covers float4 indices tid*2, tid*2+1 of the 16x64 tile
    const int bk0 = (tid * 2) / 16, bn0 = (tid * 2) % 16;
    const int bk1 = (tid * 2 + 1) / 16, bn1 = (tid * 2 + 1) % 16;

    unsigned long long acc2[4][8];
#pragma unroll
    for (int i = 0; i < 4; i++)
#pragma unroll
        for (int j = 0; j < 8; j++) acc2[i][j] = 0ull;

    float4 ar[4];  // one full A row (16 k-values)
    float4 br0, br1;

    const int nIt = K / GBK;

    // prologue: load tile 0
#pragma unroll
    for (int j = 0; j < 4; j++)
        ar[j] = a_ok ? *(const float4*)(a_ptr + j * 4) : make_float4(0.f, 0.f, 0.f, 0.f);
    br0 = *(const float4*)(B + (size_t)bk0 * Nn + col0 + bn0 * 4);
    br1 = *(const float4*)(B + (size_t)bk1 * Nn + col0 + bn1 * 4);
    {
#pragma unroll
        for (int j = 0; j < 4; j++) {
            As[0][j * 4 + 0][tid] = ar[j].x;
            As[0][j * 4 + 1][tid] = ar[j].y;
            As[0][j * 4 + 2][tid] = ar[j].z;
            As[0][j * 4 + 3][tid] = ar[j].w;
        }
        *(float4*)&Bs[0][bk0][bn0 * 4] = make_float4(br0.x, br0.x, br0.y, br0.y);
        *(float4*)&Bs[0][bk0][bn0 * 4 + 2] = make_float4(br0.z, br0.z, br0.w, br0.w);
        *(float4*)&Bs[0][bk1][bn1 * 4] = make_float4(br1.x, br1.x, br1.y, br1.y);
        *(float4*)&Bs[0][bk1][bn1 * 4 + 2] = make_float4(br1.z, br1.z, br1.w, br1.w);
    }
    __syncthreads();

    for (int it = 0; it < nIt; it++) {
        const int buf = it & 1;
        const bool has_next = (it + 1) < nIt;
        if (has_next) {
            const int k0 = (it + 1) * GBK;
#pragma unroll
            for (int j = 0; j < 4; j++)
                ar[j] = a_ok ? *(const float4*)(a_ptr + k0 + j * 4)
                             : make_float4(0.f, 0.f, 0.f, 0.f);
            br0 = *(const float4*)(B + (size_t)(k0 + bk0) * Nn + col0 + bn0 * 4);
            br1 = *(const float4*)(B + (size_t)(k0 + bk1) * Nn + col0 + bn1 * 4);
        }
#pragma unroll
        for (int k = 0; k < GBK; k++) {
            ulonglong2 a01 = *(const ulonglong2*)&As[buf][k][ty * 8];
            ulonglong2 a23 = *(const ulonglong2*)&As[buf][k][ty * 8 + 4];
            const ulonglong2* bp = (const ulonglong2*)&Bs[buf][k][tx * 8];
            ulonglong2 b01 = bp[0], b23 = bp[1], b45 = bp[2], b67 = bp[3];
            unsigned long long av[4] = {a01.x, a01.y, a23.x, a23.y};
            unsigned long long bv[8] = {b01.x, b01.y, b23.x, b23.y,
                                        b45.x, b45.y, b67.x, b67.y};
#pragma unroll
            for (int i = 0; i < 4; i++)
#pragma unroll
                for (int j = 0; j < 8; j++) ffma2(acc2[i][j], av[i], bv[j]);
        }
        if (has_next) {
            const int nb = buf ^ 1;
#pragma unroll
            for (int j = 0; j < 4; j++) {
                As[nb][j * 4 + 0][tid] = ar[j].x;
                As[nb][j * 4 + 1][tid] = ar[j].y;
                As[nb][j * 4 + 2][tid] = ar[j].z;
                As[nb][j * 4 + 3][tid] = ar[j].w;
            }
            *(float4*)&Bs[nb][bk0][bn0 * 4] = make_float4(br0.x, br0.x, br0.y, br0.y);
            *(float4*)&Bs[nb][bk0][bn0 * 4 + 2] = make_float4(br0.z, br0.z, br0.w, br0.w);
            *(float4*)&Bs[nb][bk1][bn1 * 4] = make_float4(br1.x, br1.x, br1.y, br1.y);
            *(float4*)&Bs[nb][bk1][bn1 * 4 + 2] = make_float4(br1.z, br1.z, br1.w, br1.w);
            __syncthreads();
        }
    }

    // unpack: acc2[p][j] packs rows (2p, 2p+1) of this thread's 8x8 patch
    float accf[8][8];
#pragma unroll
    for (int p = 0; p < 4; p++)
#pragma unroll
        for (int j = 0; j < 8; j++) {
            float2 v = unpack2(acc2[p][j]);
            accf[2 * p][j] = v.x;
            accf[2 * p + 1][j] = v.y;
        }

    // store C
#pragma unroll
    for (int i = 0; i < 8; i++) {
        int row = row0 + ty * 8 + i;
        if (row < M) {
            float* cp = C + (size_t)row * Nn + col0 + tx * 8;
            *(float4*)cp = make_float4(accf[i][0], accf[i][1], accf[i][2], accf[i][3]);
            *(float4*)(cp + 4) = make_float4(accf[i][4], accf[i][5], accf[i][6], accf[i][7]);
        }
    }

    // fused attention logits (block = one head)
    float atS[8], atD[8];
#pragma unroll
    for (int j = 0; j < 8; j++) {
        atS[j] = atts[hh * 64 + tx * 8 + j];
        atD[j] = attd[hh * 64 + tx * 8 + j];
    }
    float* red = (float*)As;  // 128x8 scratch

    __syncthreads();
#pragma unroll
    for (int i = 0; i < 8; i++) {
        float p = 0.f;
#pragma unroll
        for (int j = 0; j < 8; j++) p += accf[i][j] * atS[j];
        red[(ty * 8 + i) * 8 + tx] = p;
    }
    __syncthreads();
    {
        float s = 0.f;
#pragma unroll
        for (int t = 0; t < 8; t++) s += red[tid * 8 + t];
        int node = row0 + tid;
        if (node < M) d_asrc[(size_t)node * H + hh] = s;
    }
    __syncthreads();
#pragma unroll
    for (int i = 0; i < 8; i++) {
        float p = 0.f;
#pragma unroll
        for (int j = 0; j < 8; j++) p += accf[i][j] * atD[j];
        red[(ty * 8 + i) * 8 + tx] = p;
    }
    __syncthreads();
    {
        float s = 0.f;
#pragma unroll
        for (int t = 0; t < 8; t++) s += red[tid * 8 + t];
        int node = row0 + tid;
        if (node < M) d_adst[(size_t)node * H + hh] = s;
    }
}

// ---------------- GAT aggregation: one block/graph, features+logits+edges in SMEM ----------------
template <int H, int HC, bool DOELU>
__global__ void __launch_bounds__(512)
gat_agg_smem(const float* __restrict__ h, const float* __restrict__ bias,
             float* __restrict__ out) {
    extern __shared__ float sm[];
    float* f_sh = sm;                               // NPG*HC
    float* as_sh = sm + NPG * HC;                   // NPG*H
    float* ad_sh = as_sh + NPG * H;                 // NPG*H
    int* off_sh = (int*)(ad_sh + NPG * H);          // NPG+1
    unsigned char* e_sh = (unsigned char*)(off_sh + NPG + 1);  // EMAX

    int g = blockIdx.x;
    int base = g * NPG;
    int tid = threadIdx.x;  // 512

    const float4* src4 = (const float4*)(h + (size_t)base * HC);
    float4* dst4 = (float4*)f_sh;
    for (int i = tid; i < NPG * HC / 4; i += 512) dst4[i] = src4[i];
    for (int i = tid; i < NPG * H; i += 512) {
        as_sh[i] = d_asrc[(size_t)base * H + i];
        ad_sh[i] = d_adst[(size_t)base * H + i];
    }
    for (int i = tid; i <= NPG; i += 512) off_sh[i] = d_off[base + i];
    __syncthreads();

    int beg_g = off_sh[0];
    int ne = off_sh[NPG] - beg_g;
    bool fits = (ne <= EMAX);
    if (fits)
        for (int i = tid; i < ne; i += 512)
            e_sh[i] = (unsigned char)(d_srcs[beg_g + i] - base);
    __syncthreads();

    int lane = tid & 31, w = tid >> 5;  // 16 warps
    constexpr int R = HC / 32;
    float bi[R];
#pragma unroll
    for (int k = 0; k < R; k++) bi[k] = bias[lane + 32 * k];

    for (int n = w; n < NPG; n += 16) {
        float ad[H], ssum[H];
#pragma unroll
        for (int hh = 0; hh < H; hh++) ad[hh] = ad_sh[n * H + hh];
#pragma unroll
        for (int hh = 0; hh < H; hh++)
            ssum[hh] = __expf(lrelu(as_sh[n * H + hh] + ad[hh]));  // self-loop
        float acc[R];
#pragma unroll
        for (int k = 0; k < R; k++) acc[k] = ssum[k / 2] * f_sh[n * HC + lane + 32 * k];

        int eb = off_sh[n] - beg_g, ee = off_sh[n + 1] - beg_g;
        if (fits) {
            int i = eb;
            for (; i + 1 < ee; i += 2) {
                int s0 = e_sh[i], s1 = e_sh[i + 1];
                float w0[H], w1[H];
#pragma unroll
                for (int hh = 0; hh < H; hh++) {
                    w0[hh] = __expf(lrelu(as_sh[s0 * H + hh] + ad[hh]));
                    w1[hh] = __expf(lrelu(as_sh[s1 * H + hh] + ad[hh]));
                }
#pragma unroll
                for (int hh = 0; hh < H; hh++) ssum[hh] += w0[hh] + w1[hh];
#pragma unroll
                for (int k = 0; k < R; k++)
                    acc[k] += w0[k / 2] * f_sh[s0 * HC + lane + 32 * k] +
                              w1[k / 2] * f_sh[s1 * HC + lane + 32 * k];
            }
            if (i < ee) {
                int s0 = e_sh[i];
                float w0[H];
#pragma unroll
                for (int hh = 0; hh < H; hh++) {
                    w0[hh] = __expf(lrelu(as_sh[s0 * H + hh] + ad[hh]));
                    ssum[hh] += w0[hh];
                }
#pragma unroll
                for (int k = 0; k < R; k++) acc[k] += w0[k / 2] * f_sh[s0 * HC + lane + 32 * k];
            }
        } else {  // fallback keeps correctness if a graph exceeds EMAX edges
            for (int i = eb; i < ee; i++) {
                int s0 = d_srcs[beg_g + i] - base;
                float w0[H];
#pragma unroll
                for (int hh = 0; hh < H; hh++) {
                    w0[hh] = __expf(lrelu(as_sh[s0 * H + hh] + ad[hh]));
                    ssum[hh] += w0[hh];
                }
#pragma unroll
                for (int k = 0; k < R; k++) acc[k] += w0[k / 2] * f_sh[s0 * HC + lane + 32 * k];
            }
        }
#pragma unroll
        for (int k = 0; k < R; k++) {
            float v = acc[k] / ssum[k / 2] + bi[k];
            if (DOELU) v = elu1(v);
            out[(size_t)(base + n) * HC + lane + 32 * k] = v;
        }
    }
}

// ---------------- global mean pool + concat graph_input ----------------
__global__ void pool_kernel(const float* __restrict__ h, const float* __restrict__ ginput) {
    int g = blockIdx.x, c = threadIdx.x;  // 64 threads
    const float* hp = h + (size_t)g * NPG * 64;
    float s = 0.f;
    for (int i = 0; i < NPG; i++) s += hp[i * 64 + c];
    d_pool[g * 68 + c] = s * (1.0f / NPG);
    if (c < 4) d_pool[g * 68 + 64 + c] = ginput[g * 4 + c];
}

// ---------------- fused head ----------------
__global__ void head_kernel(const float* __restrict__ bn_g, const float* __restrict__ bn_b,
                            const float* __restrict__ bn_m, const float* __restrict__ bn_v,
                            const float* __restrict__ Wd1, const float* __restrict__ bd1,
                            const float* __restrict__ Wd2, const float* __restrict__ bd2,
                            const float* __restrict__ Wo, const float* __restrict__ bo,
                            float* __restrict__ out) {
    __shared__ float sg[68], t1s[64], t2s[64];
    int g = blockIdx.x, t = threadIdx.x;  // 128 threads
    if (t < 68) {
        float v = d_pool[g * 68 + t];
        v = (v - bn_m[t]) * rsqrtf(bn_v[t] + 1e-5f) * bn_g[t] + bn_b[t];
        sg[t] = v;
    }
    __syncthreads();
    if (t < 64) {
        float a = bd1[t];
        for (int i = 0; i < 68; i++) a += sg[i] * Wd1[i * 64 + t];
        t1s[t] = seluf(a);
    }
    __syncthreads();
    if (t < 64) {
        float a = bd2[t];
        for (int i = 0; i < 64; i++) a += t1s[i] * Wd2[i * 64 + t];
        t2s[t] = seluf(a);
    }
    __syncthreads();
    if (t == 0) {
        float o0 = bo[0], o1 = bo[1];
        for (int i = 0; i < 64; i++) {
            o0 += t2s[i] * Wo[i * 2];
            o1 += t2s[i] * Wo[i * 2 + 1];
        }
        float mx = fmaxf(o0, o1);
        float e0 = expf(o0 - mx), e1 = expf(o1 - mx);
        float s = e0 + e1;
        out[g * 2] = e0 / s;
        out[g * 2 + 1] = e1 / s;
    }
}

// ---------------- launch ----------------
extern "C" void kernel_launch(void* const* d_in, const int* in_sizes, int n_in,
                              void* d_out, int out_size) {
    const float* x = (const float*)d_in[0];
    const void* ei = d_in[1];
    const float* ginput = (const float*)d_in[2];
    const float* gn_w = (const float*)d_in[4];
    const float* gn_b = (const float*)d_in[5];
    const float* gn_ms = (const float*)d_in[6];
    const float* W1 = (const float*)d_in[7];
    const float* as1 = (const float*)d_in[8];
    const float* ad1 = (const float*)d_in[9];
    const float* b1 = (const float*)d_in[10];
    const float* W2 = (const float*)d_in[11];
    const float* as2 = (const float*)d_in[12];
    const float* ad2 = (const float*)d_in[13];
    const float* b2 = (const float*)d_in[14];
    const float* W3 = (const float*)d_in[15];
    const float* as3 = (const float*)d_in[16];
    const float* ad3 = (const float*)d_in[17];
    const float* b3 = (const float*)d_in[18];
    const float* bn_g = (const float*)d_in[19];
    const float* bn_b = (const float*)d_in[20];
    const float* bn_m = (const float*)d_in[21];
    const float* bn_v = (const float*)d_in[22];
    const float* Wd1 = (const float*)d_in[23];
    const float* bd1 = (const float*)d_in[24];
    const float* Wd2 = (const float*)d_in[25];
    const float* bd2 = (const float*)d_in[26];
    const float* Wo = (const float*)d_in[27];
    const float* bo = (const float*)d_in[28];
    float* out = (float*)d_out;

    float *pH0, *pHA, *pHB;
    cudaGetSymbolAddress((void**)&pH0, d_h0);
    cudaGetSymbolAddress((void**)&pHA, d_hA);
    cudaGetSymbolAddress((void**)&pHB, d_hB);

    const int SM_BIG = (NPG * 256 + NPG * 4 * 2) * 4 + (NPG + 1) * 4 + EMAX;   // ~108 KB
    const int SM_SMALL = (NPG * 64 + NPG * 1 * 2) * 4 + (NPG + 1) * 4 + EMAX;  // ~29 KB
    cudaFuncSetAttribute(gat_agg_smem<4, 256, true>,
                         cudaFuncAttributeMaxDynamicSharedMemorySize, SM_BIG);
    cudaFuncSetAttribute(gat_agg_smem<1, 64, false>,
                         cudaFuncAttributeMaxDynamicSharedMemorySize, SM_SMALL);

    const int gridM = (NNODES + GBM - 1) / GBM;  // 391

    // (1) graphnorm  (2) init  (3) count  (4) sgemm L1  <- profiler slot
    graphnorm_kernel<<<NGRAPHS, 128>>>(x, gn_w, gn_b, gn_ms);
    init_kernel<<<(NNODES + 256) / 256, 256>>>((const int*)ei);
    count_kernel<<<(NEDGES + 255) / 256, 256>>>(ei);
    sgemm_att<<<dim3(gridM, 4), 128>>>(pH0, W1, pHA, NNODES, 16, 256, as1, ad1, 4);
    scan_blocks<<<SCAN_NBLK, 1024>>>();
    scan_sums<<<1, 64>>>();
    scan_add<<<SCAN_NBLK - 1, 1024>>>();
    scatter_kernel<<<(NEDGES + 255) / 256, 256>>>(ei);

    gat_agg_smem<4, 256, true><<<NGRAPHS, 512, SM_BIG>>>(pHA, b1, pHB);

    sgemm_att<<<dim3(gridM, 4), 128>>>(pHB, W2, pHA, NNODES, 256, 256, as2, ad2, 4);
    gat_agg_smem<4, 256, true><<<NGRAPHS, 512, SM_BIG>>>(pHA, b2, pHB);

    sgemm_att<<<dim3(gridM, 1), 128>>>(pHB, W3, pHA, NNODES, 256, 64, as3, ad3, 1);
    gat_agg_smem<1, 64, false><<<NGRAPHS, 512, SM_SMALL>>>(pHA, b3, pHB);

    pool_kernel<<<NGRAPHS, 64>>>(pHB, ginput);
    head_kernel<<<NGRAPHS, 128>>>(bn_g, bn_b, bn_m, bn_v, Wd1, bd1, Wd2, bd2, Wo, bo, out);
}

// round 5
// speedup vs baseline: 1.3088x; 1.3088x over previous
#include <cuda_runtime.h>

#define NNODES 50000
#define NEDGES 500000
#define NGRAPHS 500
#define NPG 100
#define FIN 16
#define SCAN_NBLK ((NNODES + 1 + 1023) / 1024)   // 49
#define EMAX 2048                                 // per-graph edge cap for SMEM staging

// ---------------- scratch (device globals; no allocation allowed) ----------------
__device__ float d_h0[NNODES * FIN];
__device__ float d_hA[NNODES * 256];
__device__ float d_hB[NNODES * 256];
__device__ float d_asrc[NNODES * 4];
__device__ float d_adst[NNODES * 4];
__device__ int   d_off[NNODES + 1];
__device__ int   d_cursor[NNODES];
__device__ int   d_srcs[NEDGES];
__device__ int   d_bsum[64];
__device__ float d_pool[NGRAPHS * 68];
__device__ int   d_is64;

// ---------------- small helpers ----------------
__device__ __forceinline__ float lrelu(float x) { return x > 0.f ? x : 0.2f * x; }
__device__ __forceinline__ float elu1(float x) { return x > 0.f ? x : __expf(x) - 1.f; }
__device__ __forceinline__ float seluf(float x) {
    const float a = 1.6732632423543772f, sc = 1.0507009873554805f;
    return x > 0.f ? sc * x : sc * a * expm1f(x);
}

// packed fp32x2 FMA (Blackwell; ptxas never emits this from C++)
__device__ __forceinline__ void ffma2(unsigned long long& d, unsigned long long a,
                                      unsigned long long b) {
    asm("fma.rn.f32x2 %0, %1, %2, %0;" : "+l"(d) : "l"(a), "l"(b));
}
__device__ __forceinline__ float2 unpack2(unsigned long long v) {
    float2 f;
    asm("mov.b64 {%0, %1}, %2;" : "=f"(f.x), "=f"(f.y) : "l"(v));
    return f;
}

__device__ __forceinline__ int load_edge(const void* ei, long long pos) {
    if (d_is64) return (int)((const long long*)ei)[pos];
    return ((const int*)ei)[pos];
}

// ---------------- init: dtype detect + zero counters ----------------
__global__ void init_kernel(const int* ew) {
    int i = blockIdx.x * blockDim.x + threadIdx.x;
    if (i == 0) {
        int ok = 1;
        for (int j = 1; j < 256; j += 2)
            if (ew[j] != 0) ok = 0;
        d_is64 = ok;
    }
    if (i <= NNODES) d_off[i] = 0;
    if (i < NNODES) d_cursor[i] = 0;
}

__global__ void count_kernel(const void* ei) {
    int e = blockIdx.x * blockDim.x + threadIdx.x;
    if (e < NEDGES) {
        int d = load_edge(ei, (long long)NEDGES + e);
        atomicAdd(&d_off[d + 1], 1);
    }
}

// multi-block inclusive scan
__global__ void scan_blocks() {
    __shared__ int s[1024];
    int tid = threadIdx.x;
    int idx = blockIdx.x * 1024 + tid;
    int v = (idx <= NNODES) ? d_off[idx] : 0;
    s[tid] = v;
    __syncthreads();
    for (int off = 1; off < 1024; off <<= 1) {
        int t = (tid >= off) ? s[tid - off] : 0;
        __syncthreads();
        s[tid] += t;
        __syncthreads();
    }
    if (idx <= NNODES) d_off[idx] = s[tid];
    if (tid == 1023) d_bsum[blockIdx.x] = s[1023];
}

__global__ void scan_sums() {
    __shared__ int s[64];
    int tid = threadIdx.x;
    s[tid] = (tid < SCAN_NBLK) ? d_bsum[tid] : 0;
    __syncthreads();
    for (int off = 1; off < 64; off <<= 1) {
        int t = (tid >= off) ? s[tid - off] : 0;
        __syncthreads();
        s[tid] += t;
        __syncthreads();
    }
    d_bsum[tid] = s[tid];
}

__global__ void scan_add() {
    int b = blockIdx.x + 1;
    int idx = b * 1024 + threadIdx.x;
    if (idx <= NNODES) d_off[idx] += d_bsum[b - 1];
}

__global__ void scatter_kernel(const void* ei) {
    int e = blockIdx.x * blockDim.x + threadIdx.x;
    if (e < NEDGES) {
        int sN = load_edge(ei, e);
        int d = load_edge(ei, (long long)NEDGES + e);
        int p = atomicAdd(&d_cursor[d], 1);
        d_srcs[d_off[d] + p] = sN;
    }
}

// ---------------- GraphNorm: one block per graph ----------------
__global__ void graphnorm_kernel(const float* __restrict__ x, const float* __restrict__ w,
                                 const float* __restrict__ b, const float* __restrict__ ms) {
    int g = blockIdx.x;
    __shared__ float red[8][16];
    __shared__ float mv[16], vv[16];
    int t = threadIdx.x;           // 128 threads
    int f = t & 15, i0 = t >> 4;
    const float* xg = x + (size_t)g * NPG * FIN;
    float s = 0.f;
    for (int i = i0; i < NPG; i += 8) s += xg[i * FIN + f];
    red[i0][f] = s;
    __syncthreads();
    if (t < 16) {
        float m = 0.f;
        for (int j = 0; j < 8; j++) m += red[j][t];
        mv[t] = m * (1.f / NPG);
    }
    __syncthreads();
    float mm = mv[f] * ms[f];
    float sv = 0.f;
    for (int i = i0; i < NPG; i += 8) {
        float o = xg[i * FIN + f] - mm;
        sv += o * o;
    }
    __syncthreads();
    red[i0][f] = sv;
    __syncthreads();
    if (t < 16) {
        float v = 0.f;
        for (int j = 0; j < 8; j++) v += red[j][t];
        vv[t] = v * (1.f / NPG);
    }
    __syncthreads();
    float inv = rsqrtf(vv[f] + 1e-5f) * w[f];
    float bb = b[f];
    for (int i = i0; i < NPG; i += 8) {
        float o = xg[i * FIN + f] - mm;
        d_h0[(size_t)(g * NPG + i) * FIN + f] = o * inv + bb;
    }
}

// ---------------- SGEMM (R3 skeleton): 128x64 tile, 8x4/thread, FFMA2, dup-B ----------------
// B duplicated in SMEM as float2{b,b} -> FFMA2 operands straight from LDS, no packing movs.
// Fused epilogue: d_asrc/d_adst = rowwise dot of C-tile with per-head att vectors.
template <int BK>
__global__ void __launch_bounds__(256, 2)
sgemm_att(const float* __restrict__ A, const float* __restrict__ B,
          float* __restrict__ C, int M, int K, int Nn,
          const float* __restrict__ atts, const float* __restrict__ attd, int H) {
    constexpr int BM = 128, BN = 64, TM = 8, TN = 4;
    __shared__ float As[BK][BM];
    __shared__ float2 Bs[BK][BN];   // duplicated
    const int tid = threadIdx.x;
    const int tx = tid % (BN / TN);   // 0..15
    const int ty = tid / (BN / TN);   // 0..15
    const int row0 = blockIdx.x * BM;
    const int col0 = blockIdx.y * BN;
    const int hh = blockIdx.y;

    unsigned long long acc2[TM / 2][TN];
#pragma unroll
    for (int i = 0; i < TM / 2; i++)
#pragma unroll
        for (int j = 0; j < TN; j++) acc2[i][j] = 0ull;

    for (int k0 = 0; k0 < K; k0 += BK) {
        const int numA4 = BM * BK / 4;
        for (int idx = tid; idx < numA4; idx += 256) {
            int m = idx / (BK / 4);
            int k4 = idx % (BK / 4);
            float4 v = make_float4(0.f, 0.f, 0.f, 0.f);
            int row = row0 + m;
            if (row < M) v = *(const float4*)(A + (size_t)row * K + k0 + k4 * 4);
            As[k4 * 4 + 0][m] = v.x;
            As[k4 * 4 + 1][m] = v.y;
            As[k4 * 4 + 2][m] = v.z;
            As[k4 * 4 + 3][m] = v.w;
        }
        const int numB4 = BK * BN / 4;
        for (int idx = tid; idx < numB4; idx += 256) {
            int k = idx / (BN / 4);
            int n4 = idx % (BN / 4);
            float4 v = *(const float4*)(B + (size_t)(k0 + k) * Nn + col0 + n4 * 4);
            *(float4*)&Bs[k][n4 * 4 + 0] = make_float4(v.x, v.x, v.y, v.y);
            *(float4*)&Bs[k][n4 * 4 + 2] = make_float4(v.z, v.z, v.w, v.w);
        }
        __syncthreads();
#pragma unroll
        for (int k = 0; k < BK; k++) {
            ulonglong2 a01 = *(const ulonglong2*)(&As[k][ty * TM]);
            ulonglong2 a23 = *(const ulonglong2*)(&As[k][ty * TM + 4]);
            const ulonglong2* bp = (const ulonglong2*)&Bs[k][tx * TN];
            ulonglong2 b01 = bp[0], b23 = bp[1];
            unsigned long long av[4] = {a01.x, a01.y, a23.x, a23.y};
            unsigned long long bv[4] = {b01.x, b01.y, b23.x, b23.y};
#pragma unroll
            for (int i = 0; i < 4; i++)
#pragma unroll
                for (int j = 0; j < TN; j++) ffma2(acc2[i][j], av[i], bv[j]);
        }
        __syncthreads();
    }

    float accf[TM][TN];
#pragma unroll
    for (int i2 = 0; i2 < TM / 2; i2++)
#pragma unroll
        for (int j = 0; j < TN; j++) {
            float2 p = unpack2(acc2[i2][j]);
            accf[2 * i2][j] = p.x;
            accf[2 * i2 + 1][j] = p.y;
        }

#pragma unroll
    for (int i = 0; i < TM; i++) {
        int row = row0 + ty * TM + i;
        if (row < M) {
            *(float4*)(C + (size_t)row * Nn + col0 + tx * TN) =
                make_float4(accf[i][0], accf[i][1], accf[i][2], accf[i][3]);
        }
    }

    float atS[TN], atD[TN];
#pragma unroll
    for (int j = 0; j < TN; j++) {
        atS[j] = atts[hh * 64 + tx * TN + j];
        atD[j] = attd[hh * 64 + tx * TN + j];
    }
    float* red = &As[0][0];  // >= 2048 floats scratch

    __syncthreads();
#pragma unroll
    for (int i = 0; i < TM; i++) {
        float p = accf[i][0] * atS[0] + accf[i][1] * atS[1] + accf[i][2] * atS[2] +
                  accf[i][3] * atS[3];
        red[(ty * TM + i) * 16 + tx] = p;
    }
    __syncthreads();
    if (tid < BM) {
        float s = 0.f;
        for (int t = 0; t < 16; t++) s += red[tid * 16 + t];
        int node = row0 + tid;
        if (node < M) d_asrc[(size_t)node * H + hh] = s;
    }
    __syncthreads();
#pragma unroll
    for (int i = 0; i < TM; i++) {
        float p = accf[i][0] * atD[0] + accf[i][1] * atD[1] + accf[i][2] * atD[2] +
                  accf[i][3] * atD[3];
        red[(ty * TM + i) * 16 + tx] = p;
    }
    __syncthreads();
    if (tid < BM) {
        float s = 0.f;
        for (int t = 0; t < 16; t++) s += red[tid * 16 + t];
        int node = row0 + tid;
        if (node < M) d_adst[(size_t)node * H + hh] = s;
    }
}

// ---------------- GAT aggregation: one block/graph, features+logits+edges in SMEM ----------------
template <int H, int HC, bool DOELU>
__global__ void __launch_bounds__(512)
gat_agg_smem(const float* __restrict__ h, const float* __restrict__ bias,
             float* __restrict__ out) {
    extern __shared__ float sm[];
    float* f_sh = sm;                               // NPG*HC
    float* as_sh = sm + NPG * HC;                   // NPG*H
    float* ad_sh = as_sh + NPG * H;                 // NPG*H
    int* off_sh = (int*)(ad_sh + NPG * H);          // NPG+1
    unsigned char* e_sh = (unsigned char*)(off_sh + NPG + 1);  // EMAX

    int g = blockIdx.x;
    int base = g * NPG;
    int tid = threadIdx.x;  // 512

    const float4* src4 = (const float4*)(h + (size_t)base * HC);
    float4* dst4 = (float4*)f_sh;
    for (int i = tid; i < NPG * HC / 4; i += 512) dst4[i] = src4[i];
    for (int i = tid; i < NPG * H; i += 512) {
        as_sh[i] = d_asrc[(size_t)base * H + i];
        ad_sh[i] = d_adst[(size_t)base * H + i];
    }
    for (int i = tid; i <= NPG; i += 512) off_sh[i] = d_off[base + i];
    __syncthreads();

    int beg_g = off_sh[0];
    int ne = off_sh[NPG] - beg_g;
    bool fits = (ne <= EMAX);
    if (fits)
        for (int i = tid; i < ne; i += 512)
            e_sh[i] = (unsigned char)(d_srcs[beg_g + i] - base);
    __syncthreads();

    int lane = tid & 31, w = tid >> 5;  // 16 warps
    constexpr int R = HC / 32;
    float bi[R];
#pragma unroll
    for (int k = 0; k < R; k++) bi[k] = bias[lane + 32 * k];

    for (int n = w; n < NPG; n += 16) {
        float ad[H], ssum[H];
#pragma unroll
        for (int hh = 0; hh < H; hh++) ad[hh] = ad_sh[n * H + hh];
#pragma unroll
        for (int hh = 0; hh < H; hh++)
            ssum[hh] = __expf(lrelu(as_sh[n * H + hh] + ad[hh]));  // self-loop
        float acc[R];
#pragma unroll
        for (int k = 0; k < R; k++) acc[k] = ssum[k / 2] * f_sh[n * HC + lane + 32 * k];

        int eb = off_sh[n] - beg_g, ee = off_sh[n + 1] - beg_g;
        if (fits) {
            int i = eb;
            for (; i + 1 < ee; i += 2) {
                int s0 = e_sh[i], s1 = e_sh[i + 1];
                float w0[H], w1[H];
#pragma unroll
                for (int hh = 0; hh < H; hh++) {
                    w0[hh] = __expf(lrelu(as_sh[s0 * H + hh] + ad[hh]));
                    w1[hh] = __expf(lrelu(as_sh[s1 * H + hh] + ad[hh]));
                }
#pragma unroll
                for (int hh = 0; hh < H; hh++) ssum[hh] += w0[hh] + w1[hh];
#pragma unroll
                for (int k = 0; k < R; k++)
                    acc[k] += w0[k / 2] * f_sh[s0 * HC + lane + 32 * k] +
                              w1[k / 2] * f_sh[s1 * HC + lane + 32 * k];
            }
            if (i < ee) {
                int s0 = e_sh[i];
                float w0[H];
#pragma unroll
                for (int hh = 0; hh < H; hh++) {
                    w0[hh] = __expf(lrelu(as_sh[s0 * H + hh] + ad[hh]));
                    ssum[hh] += w0[hh];
                }
#pragma unroll
                for (int k = 0; k < R; k++) acc[k] += w0[k / 2] * f_sh[s0 * HC + lane + 32 * k];
            }
        } else {  // fallback keeps correctness if a graph exceeds EMAX edges
            for (int i = eb; i < ee; i++) {
                int s0 = d_srcs[beg_g + i] - base;
                float w0[H];
#pragma unroll
                for (int hh = 0; hh < H; hh++) {
                    w0[hh] = __expf(lrelu(as_sh[s0 * H + hh] + ad[hh]));
                    ssum[hh] += w0[hh];
                }
#pragma unroll
                for (int k = 0; k < R; k++) acc[k] += w0[k / 2] * f_sh[s0 * HC + lane + 32 * k];
            }
        }
#pragma unroll
        for (int k = 0; k < R; k++) {
            float v = acc[k] / ssum[k / 2] + bi[k];
            if (DOELU) v = elu1(v);
            out[(size_t)(base + n) * HC + lane + 32 * k] = v;
        }
    }
}

// ---------------- global mean pool + concat graph_input ----------------
__global__ void pool_kernel(const float* __restrict__ h, const float* __restrict__ ginput) {
    int g = blockIdx.x, c = threadIdx.x;  // 64 threads
    const float* hp = h + (size_t)g * NPG * 64;
    float s = 0.f;
    for (int i = 0; i < NPG; i++) s += hp[i * 64 + c];
    d_pool[g * 68 + c] = s * (1.0f / NPG);
    if (c < 4) d_pool[g * 68 + 64 + c] = ginput[g * 4 + c];
}

// ---------------- fused head ----------------
__global__ void head_kernel(const float* __restrict__ bn_g, const float* __restrict__ bn_b,
                            const float* __restrict__ bn_m, const float* __restrict__ bn_v,
                            const float* __restrict__ Wd1, const float* __restrict__ bd1,
                            const float* __restrict__ Wd2, const float* __restrict__ bd2,
                            const float* __restrict__ Wo, const float* __restrict__ bo,
                            float* __restrict__ out) {
    __shared__ float sg[68], t1s[64], t2s[64];
    int g = blockIdx.x, t = threadIdx.x;  // 128 threads
    if (t < 68) {
        float v = d_pool[g * 68 + t];
        v = (v - bn_m[t]) * rsqrtf(bn_v[t] + 1e-5f) * bn_g[t] + bn_b[t];
        sg[t] = v;
    }
    __syncthreads();
    if (t < 64) {
        float a = bd1[t];
        for (int i = 0; i < 68; i++) a += sg[i] * Wd1[i * 64 + t];
        t1s[t] = seluf(a);
    }
    __syncthreads();
    if (t < 64) {
        float a = bd2[t];
        for (int i = 0; i < 64; i++) a += t1s[i] * Wd2[i * 64 + t];
        t2s[t] = seluf(a);
    }
    __syncthreads();
    if (t == 0) {
        float o0 = bo[0], o1 = bo[1];
        for (int i = 0; i < 64; i++) {
            o0 += t2s[i] * Wo[i * 2];
            o1 += t2s[i] * Wo[i * 2 + 1];
        }
        float mx = fmaxf(o0, o1);
        float e0 = expf(o0 - mx), e1 = expf(o1 - mx);
        float s = e0 + e1;
        out[g * 2] = e0 / s;
        out[g * 2 + 1] = e1 / s;
    }
}

// ---------------- launch ----------------
extern "C" void kernel_launch(void* const* d_in, const int* in_sizes, int n_in,
                              void* d_out, int out_size) {
    const float* x = (const float*)d_in[0];
    const void* ei = d_in[1];
    const float* ginput = (const float*)d_in[2];
    const float* gn_w = (const float*)d_in[4];
    const float* gn_b = (const float*)d_in[5];
    const float* gn_ms = (const float*)d_in[6];
    const float* W1 = (const float*)d_in[7];
    const float* as1 = (const float*)d_in[8];
    const float* ad1 = (const float*)d_in[9];
    const float* b1 = (const float*)d_in[10];
    const float* W2 = (const float*)d_in[11];
    const float* as2 = (const float*)d_in[12];
    const float* ad2 = (const float*)d_in[13];
    const float* b2 = (const float*)d_in[14];
    const float* W3 = (const float*)d_in[15];
    const float* as3 = (const float*)d_in[16];
    const float* ad3 = (const float*)d_in[17];
    const float* b3 = (const float*)d_in[18];
    const float* bn_g = (const float*)d_in[19];
    const float* bn_b = (const float*)d_in[20];
    const float* bn_m = (const float*)d_in[21];
    const float* bn_v = (const float*)d_in[22];
    const float* Wd1 = (const float*)d_in[23];
    const float* bd1 = (const float*)d_in[24];
    const float* Wd2 = (const float*)d_in[25];
    const float* bd2 = (const float*)d_in[26];
    const float* Wo = (const float*)d_in[27];
    const float* bo = (const float*)d_in[28];
    float* out = (float*)d_out;

    float *pH0, *pHA, *pHB;
    cudaGetSymbolAddress((void**)&pH0, d_h0);
    cudaGetSymbolAddress((void**)&pHA, d_hA);
    cudaGetSymbolAddress((void**)&pHB, d_hB);

    const int SM_BIG = (NPG * 256 + NPG * 4 * 2) * 4 + (NPG + 1) * 4 + EMAX;   // ~108 KB
    const int SM_SMALL = (NPG * 64 + NPG * 1 * 2) * 4 + (NPG + 1) * 4 + EMAX;  // ~29 KB
    cudaFuncSetAttribute(gat_agg_smem<4, 256, true>,
                         cudaFuncAttributeMaxDynamicSharedMemorySize, SM_BIG);
    cudaFuncSetAttribute(gat_agg_smem<1, 64, false>,
                         cudaFuncAttributeMaxDynamicSharedMemorySize, SM_SMALL);

    const int gridM = (NNODES + 127) / 128;  // 391

    // (1) graphnorm  (2) init  (3) count  (4) sgemm L1  <- profiler slot
    graphnorm_kernel<<<NGRAPHS, 128>>>(x, gn_w, gn_b, gn_ms);
    init_kernel<<<(NNODES + 256) / 256, 256>>>((const int*)ei);
    count_kernel<<<(NEDGES + 255) / 256, 256>>>(ei);
    sgemm_att<16><<<dim3(gridM, 4), 256>>>(pH0, W1, pHA, NNODES, 16, 256, as1, ad1, 4);
    scan_blocks<<<SCAN_NBLK, 1024>>>();
    scan_sums<<<1, 64>>>();
    scan_add<<<SCAN_NBLK - 1, 1024>>>();
    scatter_kernel<<<(NEDGES + 255) / 256, 256>>>(ei);

    gat_agg_smem<4, 256, true><<<NGRAPHS, 512, SM_BIG>>>(pHA, b1, pHB);

    sgemm_att<32><<<dim3(gridM, 4), 256>>>(pHB, W2, pHA, NNODES, 256, 256, as2, ad2, 4);
    gat_agg_smem<4, 256, true><<<NGRAPHS, 512, SM_BIG>>>(pHA, b2, pHB);

    sgemm_att<32><<<dim3(gridM, 1), 256>>>(pHB, W3, pHA, NNODES, 256, 64, as3, ad3, 1);
    gat_agg_smem<1, 64, false><<<NGRAPHS, 512, SM_SMALL>>>(pHA, b3, pHB);

    pool_kernel<<<NGRAPHS, 64>>>(pHB, ginput);
    head_kernel<<<NGRAPHS, 128>>>(bn_g, bn_b, bn_m, bn_v, Wd1, bd1, Wd2, bd2, Wo, bo, out);
}

// round 6
// speedup vs baseline: 1.9258x; 1.4715x over previous
#include <cuda_runtime.h>

#define NNODES 50000
#define NEDGES 500000
#define NGRAPHS 500
#define NPG 100
#define FIN 16
#define SCAN_NBLK ((NNODES + 1 + 1023) / 1024)   // 49
#define EMAX 2048                                 // per-graph edge cap for SMEM staging

// ---------------- scratch (device globals; no allocation allowed) ----------------
__device__ float d_h0[NNODES * FIN];
__device__ float d_hA[NNODES * 256];
__device__ float d_hB[NNODES * 256];
__device__ float d_asrc[NNODES * 4];
__device__ float d_adst[NNODES * 4];
__device__ int   d_off[NNODES + 1];
__device__ int   d_cursor[NNODES];
__device__ int   d_srcs[NEDGES];
__device__ int   d_bsum[64];
__device__ float d_pool[NGRAPHS * 68];
__device__ int   d_is64;

// ---------------- small helpers ----------------
__device__ __forceinline__ float lrelu(float x) { return x > 0.f ? x : 0.2f * x; }
__device__ __forceinline__ float elu1(float x) { return x > 0.f ? x : __expf(x) - 1.f; }
__device__ __forceinline__ float seluf(float x) {
    const float a = 1.6732632423543772f, sc = 1.0507009873554805f;
    return x > 0.f ? sc * x : sc * a * expm1f(x);
}

// packed fp32x2 FMA (Blackwell; ptxas never emits this from C++)
__device__ __forceinline__ void ffma2(unsigned long long& d, unsigned long long a,
                                      unsigned long long b) {
    asm("fma.rn.f32x2 %0, %1, %2, %0;" : "+l"(d) : "l"(a), "l"(b));
}
__device__ __forceinline__ unsigned long long pack2(float x, float y) {
    unsigned long long r;
    asm("mov.b64 %0, {%1, %2};" : "=l"(r) : "f"(x), "f"(y));
    return r;
}
__device__ __forceinline__ float2 unpack2(unsigned long long v) {
    float2 f;
    asm("mov.b64 {%0, %1}, %2;" : "=f"(f.x), "=f"(f.y) : "l"(v));
    return f;
}

__device__ __forceinline__ int load_edge(const void* ei, long long pos) {
    if (d_is64) return (int)((const long long*)ei)[pos];
    return ((const int*)ei)[pos];
}

// ---------------- init: dtype detect + zero counters ----------------
__global__ void init_kernel(const int* ew) {
    int i = blockIdx.x * blockDim.x + threadIdx.x;
    if (i == 0) {
        int ok = 1;
        for (int j = 1; j < 256; j += 2)
            if (ew[j] != 0) ok = 0;
        d_is64 = ok;
    }
    if (i <= NNODES) d_off[i] = 0;
    if (i < NNODES) d_cursor[i] = 0;
}

__global__ void count_kernel(const void* ei) {
    int e = blockIdx.x * blockDim.x + threadIdx.x;
    if (e < NEDGES) {
        int d = load_edge(ei, (long long)NEDGES + e);
        atomicAdd(&d_off[d + 1], 1);
    }
}

// multi-block inclusive scan
__global__ void scan_blocks() {
    __shared__ int s[1024];
    int tid = threadIdx.x;
    int idx = blockIdx.x * 1024 + tid;
    int v = (idx <= NNODES) ? d_off[idx] : 0;
    s[tid] = v;
    __syncthreads();
    for (int off = 1; off < 1024; off <<= 1) {
        int t = (tid >= off) ? s[tid - off] : 0;
        __syncthreads();
        s[tid] += t;
        __syncthreads();
    }
    if (idx <= NNODES) d_off[idx] = s[tid];
    if (tid == 1023) d_bsum[blockIdx.x] = s[1023];
}

__global__ void scan_sums() {
    __shared__ int s[64];
    int tid = threadIdx.x;
    s[tid] = (tid < SCAN_NBLK) ? d_bsum[tid] : 0;
    __syncthreads();
    for (int off = 1; off < 64; off <<= 1) {
        int t = (tid >= off) ? s[tid - off] : 0;
        __syncthreads();
        s[tid] += t;
        __syncthreads();
    }
    d_bsum[tid] = s[tid];
}

__global__ void scan_add() {
    int b = blockIdx.x + 1;
    int idx = b * 1024 + threadIdx.x;
    if (idx <= NNODES) d_off[idx] += d_bsum[b - 1];
}

__global__ void scatter_kernel(const void* ei) {
    int e = blockIdx.x * blockDim.x + threadIdx.x;
    if (e < NEDGES) {
        int sN = load_edge(ei, e);
        int d = load_edge(ei, (long long)NEDGES + e);
        int p = atomicAdd(&d_cursor[d], 1);
        d_srcs[d_off[d] + p] = sN;
    }
}

// ---------------- GraphNorm: one block per graph ----------------
__global__ void graphnorm_kernel(const float* __restrict__ x, const float* __restrict__ w,
                                 const float* __restrict__ b, const float* __restrict__ ms) {
    int g = blockIdx.x;
    __shared__ float red[8][16];
    __shared__ float mv[16], vv[16];
    int t = threadIdx.x;           // 128 threads
    int f = t & 15, i0 = t >> 4;
    const float* xg = x + (size_t)g * NPG * FIN;
    float s = 0.f;
    for (int i = i0; i < NPG; i += 8) s += xg[i * FIN + f];
    red[i0][f] = s;
    __syncthreads();
    if (t < 16) {
        float m = 0.f;
        for (int j = 0; j < 8; j++) m += red[j][t];
        mv[t] = m * (1.f / NPG);
    }
    __syncthreads();
    float mm = mv[f] * ms[f];
    float sv = 0.f;
    for (int i = i0; i < NPG; i += 8) {
        float o = xg[i * FIN + f] - mm;
        sv += o * o;
    }
    __syncthreads();
    red[i0][f] = sv;
    __syncthreads();
    if (t < 16) {
        float v = 0.f;
        for (int j = 0; j < 8; j++) v += red[j][t];
        vv[t] = v * (1.f / NPG);
    }
    __syncthreads();
    float inv = rsqrtf(vv[f] + 1e-5f) * w[f];
    float bb = b[f];
    for (int i = i0; i < NPG; i += 8) {
        float o = xg[i * FIN + f] - mm;
        d_h0[(size_t)(g * NPG + i) * FIN + f] = o * inv + bb;
    }
}

// ---------------- SGEMM: 128x64 tile, 128 threads, 8x8/thread, FFMA2 ----------------
// Plain-B SMEM (pack movs are cheaper than extra LDS bytes — measured R5).
// No accf materialization: unpack per row-pair in epilogue (avoids R4's spills).
// Fused epilogue: d_asrc/d_adst = rowwise dot of C-tile with per-head att vectors.
__global__ void __launch_bounds__(128, 3)
sgemm_att(const float* __restrict__ A, const float* __restrict__ B,
          float* __restrict__ C, int M, int K, int Nn,
          const float* __restrict__ atts, const float* __restrict__ attd, int H) {
    constexpr int BM = 128, BN = 64, BK = 16;
    __shared__ float As[BK][BM];   // 8 KB
    __shared__ float Bs[BK][BN];   // 4 KB
    const int tid = threadIdx.x;   // 128
    const int tx = tid & 7;        // 8 col groups (8 cols)
    const int ty = tid >> 3;       // 16 row groups (8 rows)
    const int row0 = blockIdx.x * BM;
    const int col0 = blockIdx.y * BN;
    const int hh = blockIdx.y;

    unsigned long long acc2[4][8];  // 4 row-pairs x 8 cols
#pragma unroll
    for (int i = 0; i < 4; i++)
#pragma unroll
        for (int j = 0; j < 8; j++) acc2[i][j] = 0ull;

    for (int k0 = 0; k0 < K; k0 += BK) {
        // A tile: 512 float4 / 128 threads = 4 iterations, transpose into As[k][m]
#pragma unroll
        for (int it = 0; it < 4; it++) {
            int idx = tid + it * 128;
            int m = idx >> 2;         // 0..127
            int k4 = idx & 3;         // 0..3
            float4 v = make_float4(0.f, 0.f, 0.f, 0.f);
            int row = row0 + m;
            if (row < M) v = *(const float4*)(A + (size_t)row * K + k0 + k4 * 4);
            As[k4 * 4 + 0][m] = v.x;
            As[k4 * 4 + 1][m] = v.y;
            As[k4 * 4 + 2][m] = v.z;
            As[k4 * 4 + 3][m] = v.w;
        }
        // B tile: 256 float4 / 128 threads = 2 iterations
#pragma unroll
        for (int it = 0; it < 2; it++) {
            int idx = tid + it * 128;
            int k = idx >> 4;         // 0..15
            int n4 = idx & 15;        // 0..15
            *(float4*)(&Bs[k][n4 * 4]) =
                *(const float4*)(B + (size_t)(k0 + k) * Nn + col0 + n4 * 4);
        }
        __syncthreads();
#pragma unroll
        for (int k = 0; k < BK; k++) {
            ulonglong2 a01 = *(const ulonglong2*)(&As[k][ty * 8]);
            ulonglong2 a23 = *(const ulonglong2*)(&As[k][ty * 8 + 4]);
            float4 bva = *(const float4*)(&Bs[k][tx * 8]);
            float4 bvb = *(const float4*)(&Bs[k][tx * 8 + 4]);
            unsigned long long av[4] = {a01.x, a01.y, a23.x, a23.y};
            unsigned long long bv[8];
            bv[0] = pack2(bva.x, bva.x);
            bv[1] = pack2(bva.y, bva.y);
            bv[2] = pack2(bva.z, bva.z);
            bv[3] = pack2(bva.w, bva.w);
            bv[4] = pack2(bvb.x, bvb.x);
            bv[5] = pack2(bvb.y, bvb.y);
            bv[6] = pack2(bvb.z, bvb.z);
            bv[7] = pack2(bvb.w, bvb.w);
#pragma unroll
            for (int i = 0; i < 4; i++)
#pragma unroll
                for (int j = 0; j < 8; j++) ffma2(acc2[i][j], av[i], bv[j]);
        }
        __syncthreads();
    }

    // epilogue: per row-pair, unpack, store C, compute att dots (no accf array)
    float atS[8], atD[8];
#pragma unroll
    for (int j = 0; j < 8; j++) {
        atS[j] = atts[hh * 64 + tx * 8 + j];
        atD[j] = attd[hh * 64 + tx * 8 + j];
    }
    float* redS = &As[0][0];           // 1024 floats
    float* redD = &As[0][0] + 1024;    // 1024 floats (As is 2048 total)

    __syncthreads();
#pragma unroll
    for (int p = 0; p < 4; p++) {
        float v0[8], v1[8];
#pragma unroll
        for (int j = 0; j < 8; j++) {
            float2 u = unpack2(acc2[p][j]);
            v0[j] = u.x;
            v1[j] = u.y;
        }
        int r0 = row0 + ty * 8 + 2 * p;
        if (r0 < M) {
            float* cp = C + (size_t)r0 * Nn + col0 + tx * 8;
            *(float4*)cp = make_float4(v0[0], v0[1], v0[2], v0[3]);
            *(float4*)(cp + 4) = make_float4(v0[4], v0[5], v0[6], v0[7]);
        }
        int r1 = r0 + 1;
        if (r1 < M) {
            float* cp = C + (size_t)r1 * Nn + col0 + tx * 8;
            *(float4*)cp = make_float4(v1[0], v1[1], v1[2], v1[3]);
            *(float4*)(cp + 4) = make_float4(v1[4], v1[5], v1[6], v1[7]);
        }
        float s0 = 0.f, d0 = 0.f, s1 = 0.f, d1 = 0.f;
#pragma unroll
        for (int j = 0; j < 8; j++) {
            s0 += v0[j] * atS[j];
            d0 += v0[j] * atD[j];
            s1 += v1[j] * atS[j];
            d1 += v1[j] * atD[j];
        }
        redS[(ty * 8 + 2 * p) * 8 + tx] = s0;
        redD[(ty * 8 + 2 * p) * 8 + tx] = d0;
        redS[(ty * 8 + 2 * p + 1) * 8 + tx] = s1;
        redD[(ty * 8 + 2 * p + 1) * 8 + tx] = d1;
    }
    __syncthreads();
    {
        float s = 0.f, d = 0.f;
#pragma unroll
        for (int t = 0; t < 8; t++) {
            s += redS[tid * 8 + t];
            d += redD[tid * 8 + t];
        }
        int node = row0 + tid;
        if (node < M) {
            d_asrc[(size_t)node * H + hh] = s;
            d_adst[(size_t)node * H + hh] = d;
        }
    }
}

// ---------------- GAT aggregation: one block/graph, features+logits+edges in SMEM ----------------
template <int H, int HC, bool DOELU>
__global__ void __launch_bounds__(512)
gat_agg_smem(const float* __restrict__ h, const float* __restrict__ bias,
             float* __restrict__ out) {
    extern __shared__ float sm[];
    float* f_sh = sm;                               // NPG*HC
    float* as_sh = sm + NPG * HC;                   // NPG*H
    float* ad_sh = as_sh + NPG * H;                 // NPG*H
    int* off_sh = (int*)(ad_sh + NPG * H);          // NPG+1
    unsigned char* e_sh = (unsigned char*)(off_sh + NPG + 1);  // EMAX

    int g = blockIdx.x;
    int base = g * NPG;
    int tid = threadIdx.x;  // 512

    const float4* src4 = (const float4*)(h + (size_t)base * HC);
    float4* dst4 = (float4*)f_sh;
    for (int i = tid; i < NPG * HC / 4; i += 512) dst4[i] = src4[i];
    for (int i = tid; i < NPG * H; i += 512) {
        as_sh[i] = d_asrc[(size_t)base * H + i];
        ad_sh[i] = d_adst[(size_t)base * H + i];
    }
    for (int i = tid; i <= NPG; i += 512) off_sh[i] = d_off[base + i];
    __syncthreads();

    int beg_g = off_sh[0];
    int ne = off_sh[NPG] - beg_g;
    bool fits = (ne <= EMAX);
    if (fits)
        for (int i = tid; i < ne; i += 512)
            e_sh[i] = (unsigned char)(d_srcs[beg_g + i] - base);
    __syncthreads();

    int lane = tid & 31, w = tid >> 5;  // 16 warps
    constexpr int R = HC / 32;
    float bi[R];
#pragma unroll
    for (int k = 0; k < R; k++) bi[k] = bias[lane + 32 * k];

    for (int n = w; n < NPG; n += 16) {
        float ad[H], ssum[H];
#pragma unroll
        for (int hh = 0; hh < H; hh++) ad[hh] = ad_sh[n * H + hh];
#pragma unroll
        for (int hh = 0; hh < H; hh++)
            ssum[hh] = __expf(lrelu(as_sh[n * H + hh] + ad[hh]));  // self-loop
        float acc[R];
#pragma unroll
        for (int k = 0; k < R; k++) acc[k] = ssum[k / 2] * f_sh[n * HC + lane + 32 * k];

        int eb = off_sh[n] - beg_g, ee = off_sh[n + 1] - beg_g;
        if (fits) {
            int i = eb;
            for (; i + 1 < ee; i += 2) {
                int s0 = e_sh[i], s1 = e_sh[i + 1];
                float w0[H], w1[H];
#pragma unroll
                for (int hh = 0; hh < H; hh++) {
                    w0[hh] = __expf(lrelu(as_sh[s0 * H + hh] + ad[hh]));
                    w1[hh] = __expf(lrelu(as_sh[s1 * H + hh] + ad[hh]));
                }
#pragma unroll
                for (int hh = 0; hh < H; hh++) ssum[hh] += w0[hh] + w1[hh];
#pragma unroll
                for (int k = 0; k < R; k++)
                    acc[k] += w0[k / 2] * f_sh[s0 * HC + lane + 32 * k] +
                              w1[k / 2] * f_sh[s1 * HC + lane + 32 * k];
            }
            if (i < ee) {
                int s0 = e_sh[i];
                float w0[H];
#pragma unroll
                for (int hh = 0; hh < H; hh++) {
                    w0[hh] = __expf(lrelu(as_sh[s0 * H + hh] + ad[hh]));
                    ssum[hh] += w0[hh];
                }
#pragma unroll
                for (int k = 0; k < R; k++) acc[k] += w0[k / 2] * f_sh[s0 * HC + lane + 32 * k];
            }
        } else {  // fallback keeps correctness if a graph exceeds EMAX edges
            for (int i = eb; i < ee; i++) {
                int s0 = d_srcs[beg_g + i] - base;
                float w0[H];
#pragma unroll
                for (int hh = 0; hh < H; hh++) {
                    w0[hh] = __expf(lrelu(as_sh[s0 * H + hh] + ad[hh]));
                    ssum[hh] += w0[hh];
                }
#pragma unroll
                for (int k = 0; k < R; k++) acc[k] += w0[k / 2] * f_sh[s0 * HC + lane + 32 * k];
            }
        }
#pragma unroll
        for (int k = 0; k < R; k++) {
            float v = acc[k] / ssum[k / 2] + bi[k];
            if (DOELU) v = elu1(v);
            out[(size_t)(base + n) * HC + lane + 32 * k] = v;
        }
    }
}

// ---------------- global mean pool + concat graph_input ----------------
__global__ void pool_kernel(const float* __restrict__ h, const float* __restrict__ ginput) {
    int g = blockIdx.x, c = threadIdx.x;  // 64 threads
    const float* hp = h + (size_t)g * NPG * 64;
    float s = 0.f;
    for (int i = 0; i < NPG; i++) s += hp[i * 64 + c];
    d_pool[g * 68 + c] = s * (1.0f / NPG);
    if (c < 4) d_pool[g * 68 + 64 + c] = ginput[g * 4 + c];
}

// ---------------- fused head ----------------
__global__ void head_kernel(const float* __restrict__ bn_g, const float* __restrict__ bn_b,
                            const float* __restrict__ bn_m, const float* __restrict__ bn_v,
                            const float* __restrict__ Wd1, const float* __restrict__ bd1,
                            const float* __restrict__ Wd2, const float* __restrict__ bd2,
                            const float* __restrict__ Wo, const float* __restrict__ bo,
                            float* __restrict__ out) {
    __shared__ float sg[68], t1s[64], t2s[64];
    int g = blockIdx.x, t = threadIdx.x;  // 128 threads
    if (t < 68) {
        float v = d_pool[g * 68 + t];
        v = (v - bn_m[t]) * rsqrtf(bn_v[t] + 1e-5f) * bn_g[t] + bn_b[t];
        sg[t] = v;
    }
    __syncthreads();
    if (t < 64) {
        float a = bd1[t];
        for (int i = 0; i < 68; i++) a += sg[i] * Wd1[i * 64 + t];
        t1s[t] = seluf(a);
    }
    __syncthreads();
    if (t < 64) {
        float a = bd2[t];
        for (int i = 0; i < 64; i++) a += t1s[i] * Wd2[i * 64 + t];
        t2s[t] = seluf(a);
    }
    __syncthreads();
    if (t == 0) {
        float o0 = bo[0], o1 = bo[1];
        for (int i = 0; i < 64; i++) {
            o0 += t2s[i] * Wo[i * 2];
            o1 += t2s[i] * Wo[i * 2 + 1];
        }
        float mx = fmaxf(o0, o1);
        float e0 = expf(o0 - mx), e1 = expf(o1 - mx);
        float s = e0 + e1;
        out[g * 2] = e0 / s;
        out[g * 2 + 1] = e1 / s;
    }
}

// ---------------- launch ----------------
extern "C" void kernel_launch(void* const* d_in, const int* in_sizes, int n_in,
                              void* d_out, int out_size) {
    const float* x = (const float*)d_in[0];
    const void* ei = d_in[1];
    const float* ginput = (const float*)d_in[2];
    const float* gn_w = (const float*)d_in[4];
    const float* gn_b = (const float*)d_in[5];
    const float* gn_ms = (const float*)d_in[6];
    const float* W1 = (const float*)d_in[7];
    const float* as1 = (const float*)d_in[8];
    const float* ad1 = (const float*)d_in[9];
    const float* b1 = (const float*)d_in[10];
    const float* W2 = (const float*)d_in[11];
    const float* as2 = (const float*)d_in[12];
    const float* ad2 = (const float*)d_in[13];
    const float* b2 = (const float*)d_in[14];
    const float* W3 = (const float*)d_in[15];
    const float* as3 = (const float*)d_in[16];
    const float* ad3 = (const float*)d_in[17];
    const float* b3 = (const float*)d_in[18];
    const float* bn_g = (const float*)d_in[19];
    const float* bn_b = (const float*)d_in[20];
    const float* bn_m = (const float*)d_in[21];
    const float* bn_v = (const float*)d_in[22];
    const float* Wd1 = (const float*)d_in[23];
    const float* bd1 = (const float*)d_in[24];
    const float* Wd2 = (const float*)d_in[25];
    const float* bd2 = (const float*)d_in[26];
    const float* Wo = (const float*)d_in[27];
    const float* bo = (const float*)d_in[28];
    float* out = (float*)d_out;

    float *pH0, *pHA, *pHB;
    cudaGetSymbolAddress((void**)&pH0, d_h0);
    cudaGetSymbolAddress((void**)&pHA, d_hA);
    cudaGetSymbolAddress((void**)&pHB, d_hB);

    const int SM_BIG = (NPG * 256 + NPG * 4 * 2) * 4 + (NPG + 1) * 4 + EMAX;   // ~108 KB
    const int SM_SMALL = (NPG * 64 + NPG * 1 * 2) * 4 + (NPG + 1) * 4 + EMAX;  // ~29 KB
    cudaFuncSetAttribute(gat_agg_smem<4, 256, true>,
                         cudaFuncAttributeMaxDynamicSharedMemorySize, SM_BIG);
    cudaFuncSetAttribute(gat_agg_smem<1, 64, false>,
                         cudaFuncAttributeMaxDynamicSharedMemorySize, SM_SMALL);

    const int gridM = (NNODES + 127) / 128;  // 391

    // (1) graphnorm  (2) init  (3) count  (4) sgemm L1  <- profiler slot
    graphnorm_kernel<<<NGRAPHS, 128>>>(x, gn_w, gn_b, gn_ms);
    init_kernel<<<(NNODES + 256) / 256, 256>>>((const int*)ei);
    count_kernel<<<(NEDGES + 255) / 256, 256>>>(ei);
    sgemm_att<<<dim3(gridM, 4), 128>>>(pH0, W1, pHA, NNODES, 16, 256, as1, ad1, 4);
    scan_blocks<<<SCAN_NBLK, 1024>>>();
    scan_sums<<<1, 64>>>();
    scan_add<<<SCAN_NBLK - 1, 1024>>>();
    scatter_kernel<<<(NEDGES + 255) / 256, 256>>>(ei);

    gat_agg_smem<4, 256, true><<<NGRAPHS, 512, SM_BIG>>>(pHA, b1, pHB);

    sgemm_att<<<dim3(gridM, 4), 128>>>(pHB, W2, pHA, NNODES, 256, 256, as2, ad2, 4);
    gat_agg_smem<4, 256, true><<<NGRAPHS, 512, SM_BIG>>>(pHA, b2, pHB);

    sgemm_att<<<dim3(gridM, 1), 128>>>(pHB, W3, pHA, NNODES, 256, 64, as3, ad3, 1);
    gat_agg_smem<1, 64, false><<<NGRAPHS, 512, SM_SMALL>>>(pHA, b3, pHB);

    pool_kernel<<<NGRAPHS, 64>>>(pHB, ginput);
    head_kernel<<<NGRAPHS, 128>>>(bn_g, bn_b, bn_m, bn_v, Wd1, bd1, Wd2, bd2, Wo, bo, out);
}